// round 14
// baseline (speedup 1.0000x reference)
#include <cuda_runtime.h>
#include <cuda_fp16.h>
#include <cstddef>
#include <cstdint>

// ---------------------------------------------------------------------------
// GMM (MoNet) graph conv — 3-kernel pipeline:
//   T1:  y1 = x*W1 via mma.sync (fp16), unpadded 192B rows
//   G1H: h[n] = gather(y1) -> stored fp16 (64B rows)
//   G2:  zz[n,3,32] = gather(h) (64B/edge, 1 LDG.128/edge-lane),
//        then fused per-node GEMM out = zz·W2flat  (k-mix commuted past W2)
// ---------------------------------------------------------------------------

#define MAXN 131072
__device__ __half g_y1[MAXN * 96];   // [N][3][32]  unpadded, 192B rows
__device__ uint4  g_h [MAXN * 4];    // h fp16: [N][32] halves = [N][4] uint4 (64B rows)

typedef unsigned long long ull;

__device__ __forceinline__ ull pk2(float x, float y) {
    ull r; asm("mov.b64 %0, {%1,%2};" : "=l"(r) : "f"(x), "f"(y)); return r;
}
__device__ __forceinline__ void upk2(ull v, float& x, float& y) {
    asm("mov.b64 {%0,%1}, %2;" : "=f"(x), "=f"(y) : "l"(v));
}
__device__ __forceinline__ void ffma2(ull& d, ull a, ull b) {
    asm("fma.rn.f32x2 %0, %1, %2, %0;" : "+l"(d) : "l"(a), "l"(b));
}

__device__ __forceinline__ void ldsm_x4(uint32_t& r0, uint32_t& r1,
                                        uint32_t& r2, uint32_t& r3, uint32_t a) {
    asm volatile("ldmatrix.sync.aligned.m8n8.x4.shared.b16 {%0,%1,%2,%3}, [%4];"
                 : "=r"(r0), "=r"(r1), "=r"(r2), "=r"(r3) : "r"(a));
}
__device__ __forceinline__ void ldsm_x2_t(uint32_t& r0, uint32_t& r1, uint32_t a) {
    asm volatile("ldmatrix.sync.aligned.m8n8.x2.trans.shared.b16 {%0,%1}, [%2];"
                 : "=r"(r0), "=r"(r1) : "r"(a));
}
__device__ __forceinline__ void mma16816(float* c,
    uint32_t a0, uint32_t a1, uint32_t a2, uint32_t a3, uint32_t b0, uint32_t b1) {
    asm volatile(
        "mma.sync.aligned.m16n8k16.row.col.f32.f16.f16.f32 "
        "{%0,%1,%2,%3}, {%4,%5,%6,%7}, {%8,%9}, {%0,%1,%2,%3};"
        : "+f"(c[0]), "+f"(c[1]), "+f"(c[2]), "+f"(c[3])
        : "r"(a0), "r"(a1), "r"(a2), "r"(a3), "r"(b0), "r"(b1));
}

// ======================= T1: tensor-core transform (unchanged) =============
__global__ void __launch_bounds__(256)
t1_mma_kernel(const float* __restrict__ X, const float* __restrict__ W,
              uint4* __restrict__ Yg, int n_nodes)
{
    constexpr int MT   = 64;
    constexpr int XSTR = 72;
    constexpr int WSTR = 104;
    constexpr int SSTR = 52;

    __shared__ __half  Xh[MT * XSTR];
    __shared__ __half  Wh[64 * WSTR];
    __shared__ __half2 Ys[MT * SSTR];

    const int tid = threadIdx.x;
    const int mt0 = blockIdx.x * MT;

    for (int i = tid; i < 64 * 96; i += 256) {
        const int f = i / 96, j = i % 96;
        Wh[f * WSTR + j] = __float2half(W[((size_t)(j >> 5) * 64 + f) * 32 + (j & 31)]);
    }
    #pragma unroll
    for (int k = 0; k < 4; k++) {
        const int i = tid + k * 256;
        const int m = i >> 4, f4 = i & 15;
        float4 v = make_float4(0.f, 0.f, 0.f, 0.f);
        if (mt0 + m < n_nodes)
            v = *(const float4*)(X + (size_t)(mt0 + m) * 64 + 4 * f4);
        uint2 hv;
        __half2 h0 = __floats2half2_rn(v.x, v.y);
        __half2 h1 = __floats2half2_rn(v.z, v.w);
        hv.x = *(const uint32_t*)&h0;
        hv.y = *(const uint32_t*)&h1;
        *(uint2*)&Xh[m * XSTR + 4 * f4] = hv;
    }
    __syncthreads();

    const int lane = tid & 31;
    const int wid  = tid >> 5;
    const int wm = wid >> 1;
    const int wn = wid & 1;
    const int g = lane >> 2, t = lane & 3;

    float acc[6][4];
    #pragma unroll
    for (int ni = 0; ni < 6; ni++)
        #pragma unroll
        for (int c = 0; c < 4; c++) acc[ni][c] = 0.f;

    const uint32_t xbase = (uint32_t)__cvta_generic_to_shared(Xh);
    const uint32_t wbase = (uint32_t)__cvta_generic_to_shared(Wh);
    const int arow  = wm * 16 + (lane & 15);
    const int acol8 = 8 * (lane >> 4);
    const int brow  = lane & 15;

    #pragma unroll
    for (int kt = 0; kt < 4; kt++) {
        const int k0 = kt * 16;
        uint32_t a0, a1, a2, a3;
        ldsm_x4(a0, a1, a2, a3, xbase + (arow * XSTR + k0 + acol8) * 2);
        #pragma unroll
        for (int ni = 0; ni < 6; ni++) {
            uint32_t b0, b1;
            ldsm_x2_t(b0, b1, wbase + ((k0 + brow) * WSTR + wn * 48 + ni * 8) * 2);
            mma16816(acc[ni], a0, a1, a2, a3, b0, b1);
        }
    }

    #pragma unroll
    for (int ni = 0; ni < 6; ni++) {
        const int cidx = wn * 24 + ni * 4 + t;
        Ys[(wm * 16 + g)     * SSTR + cidx] = __floats2half2_rn(acc[ni][0], acc[ni][1]);
        Ys[(wm * 16 + g + 8) * SSTR + cidx] = __floats2half2_rn(acc[ni][2], acc[ni][3]);
    }
    __syncthreads();

    const uint4* Ysv = (const uint4*)Ys;
    #pragma unroll
    for (int k = 0; k < 3; k++) {
        const int i = tid + k * 256;
        const int r = i / 12, c = i % 12;
        if (mt0 + r < n_nodes)
            Yg[(size_t)(mt0 + r) * 12 + c] = Ysv[r * 13 + c];
    }
}

// ============================== gaussians ==================================
#define LOAD_GAUSS_PARAMS()                                                   \
    const float m0_ = mu[0], m1_ = mu[1], m2_ = mu[2],                        \
                m3_ = mu[3], m4_ = mu[4], m5_ = mu[5];                        \
    float s_;                                                                 \
    s_ = sigma[0]; const float i0_ = 1.f/(s_*s_);                             \
    s_ = sigma[1]; const float i1_ = 1.f/(s_*s_);                             \
    s_ = sigma[2]; const float i2_ = 1.f/(s_*s_);                             \
    s_ = sigma[3]; const float i3_ = 1.f/(s_*s_);                             \
    s_ = sigma[4]; const float i4_ = 1.f/(s_*s_);                             \
    s_ = sigma[5]; const float i5_ = 1.f/(s_*s_);

#define GAUSS3(pv, g0, g1, g2) do {                                           \
    float dx_, dy_, q_;                                                       \
    dx_ = (pv).x - m0_; dy_ = (pv).y - m1_;                                   \
    q_ = dx_*dx_*i0_ + dy_*dy_*i1_; g0 = __expf(-0.5f * q_);                  \
    dx_ = (pv).x - m2_; dy_ = (pv).y - m3_;                                   \
    q_ = dx_*dx_*i2_ + dy_*dy_*i3_; g1 = __expf(-0.5f * q_);                  \
    dx_ = (pv).x - m4_; dy_ = (pv).y - m5_;                                   \
    q_ = dx_*dx_*i4_ + dy_*dy_*i5_; g2 = __expf(-0.5f * q_);                  \
} while (0)

// ============== G1H: gather(y1) -> h fp16 (64B rows) =======================
// 8 lanes/node, 3x LDG.64/edge; epilogue stores fp16 h row (STG.64/lane).
template<int NWARP, int GRP>
__global__ void __launch_bounds__(NWARP * 32)
g1h_kernel(const int* __restrict__ row_ptr, const int* __restrict__ col_idx,
           const float2* __restrict__ p,
           const float* __restrict__ mu, const float* __restrict__ sigma,
           const uint2* __restrict__ y,      // y1: [N][24] uint2
           uint2* __restrict__ hout,         // h: [N][8] uint2 (fp16)
           int n_nodes)
{
    constexpr int CAP = GRP * 16;
    __shared__ float4 stg[NWARP][CAP];

    const int tid  = threadIdx.x;
    const int lane = tid & 31;
    const int wid  = tid >> 5;

    const int base = (blockIdx.x * NWARP + wid) * GRP;
    if (base >= n_nodes) return;

    LOAD_GAUSS_PARAMS();

    const int ng   = min(GRP, n_nodes - base);
    const int e0   = row_ptr[base];
    const int ecnt = row_ptr[base + ng] - e0;
    const bool fast = (ecnt <= CAP);

    if (fast) {
        for (int j = lane; j < ecnt; j += 32) {
            const int e = e0 + j;
            const int c = col_idx[e];
            const float2 pv = __ldg(p + e);
            float g0, g1, g2; GAUSS3(pv, g0, g1, g2);
            stg[wid][j] = make_float4(g0, g1, g2, __int_as_float(c));
        }
    }
    __syncwarp();

    const int s  = lane >> 3;
    const int hl = lane & 7;

    #pragma unroll
    for (int pi = 0; pi < GRP / 4; pi++) {
        const int n = base + pi * 4 + s;
        const bool valid = (n < n_nodes);
        const int nc  = valid ? n : base;
        const int st  = __ldg(row_ptr + nc);
        const int deg = valid ? (__ldg(row_ptr + nc + 1) - st) : 0;

        ull a[3][2];
        #pragma unroll
        for (int k = 0; k < 3; k++) { a[k][0] = 0ull; a[k][1] = 0ull; }

        if (fast) {
            const float4* sd = &stg[wid][st - e0];
            const bool u16 = __all_sync(0xffffffffu, deg == 16);
            #define G1_BODY(J) do {                                           \
                const float4 ed = sd[(J)];                                    \
                const int c = __float_as_int(ed.w);                           \
                const uint2* yr = y + (size_t)c * 24 + hl;                    \
                const uint2 v0 = __ldg(yr);                                   \
                const uint2 v1 = __ldg(yr + 8);                               \
                const uint2 v2 = __ldg(yr + 16);                              \
                const float2 c00 = __half22float2(*(const __half2*)&v0.x);    \
                const float2 c01 = __half22float2(*(const __half2*)&v0.y);    \
                const float2 c10 = __half22float2(*(const __half2*)&v1.x);    \
                const float2 c11 = __half22float2(*(const __half2*)&v1.y);    \
                const float2 c20 = __half22float2(*(const __half2*)&v2.x);    \
                const float2 c21 = __half22float2(*(const __half2*)&v2.y);    \
                const ull w0 = pk2(ed.x, ed.x);                               \
                const ull w1 = pk2(ed.y, ed.y);                               \
                const ull w2 = pk2(ed.z, ed.z);                               \
                ffma2(a[0][0], w0, pk2(c00.x, c00.y));                        \
                ffma2(a[0][1], w0, pk2(c01.x, c01.y));                        \
                ffma2(a[1][0], w1, pk2(c10.x, c10.y));                        \
                ffma2(a[1][1], w1, pk2(c11.x, c11.y));                        \
                ffma2(a[2][0], w2, pk2(c20.x, c20.y));                        \
                ffma2(a[2][1], w2, pk2(c21.x, c21.y));                        \
            } while (0)
            if (u16) {
                #pragma unroll
                for (int j = 0; j < 16; j++) G1_BODY(j);
            } else {
                const int maxd = __reduce_max_sync(0xffffffffu, deg);
                for (int j = 0; j < maxd; j++)
                    if (j < deg) G1_BODY(j);
            }
            #undef G1_BODY
        } else {
            const int maxd = __reduce_max_sync(0xffffffffu, deg);
            for (int j = 0; j < maxd; j++) {
                if (j < deg) {
                    const int e = st + j;
                    const int c = __ldg(col_idx + e);
                    const float2 pv = __ldg(p + e);
                    float g0, g1, g2; GAUSS3(pv, g0, g1, g2);
                    const uint2* yr = y + (size_t)c * 24 + hl;
                    const uint2 v0 = __ldg(yr);
                    const uint2 v1 = __ldg(yr + 8);
                    const uint2 v2 = __ldg(yr + 16);
                    const float2 c00 = __half22float2(*(const __half2*)&v0.x);
                    const float2 c01 = __half22float2(*(const __half2*)&v0.y);
                    const float2 c10 = __half22float2(*(const __half2*)&v1.x);
                    const float2 c11 = __half22float2(*(const __half2*)&v1.y);
                    const float2 c20 = __half22float2(*(const __half2*)&v2.x);
                    const float2 c21 = __half22float2(*(const __half2*)&v2.y);
                    ffma2(a[0][0], pk2(g0, g0), pk2(c00.x, c00.y));
                    ffma2(a[0][1], pk2(g0, g0), pk2(c01.x, c01.y));
                    ffma2(a[1][0], pk2(g1, g1), pk2(c10.x, c10.y));
                    ffma2(a[1][1], pk2(g1, g1), pk2(c11.x, c11.y));
                    ffma2(a[2][0], pk2(g2, g2), pk2(c20.x, c20.y));
                    ffma2(a[2][1], pk2(g2, g2), pk2(c21.x, c21.y));
                }
            }
        }

        if (valid) {
            float p00, p01, p10, p11, q00, q01, q10, q11, r00, r01, r10, r11;
            upk2(a[0][0], p00, p01); upk2(a[0][1], p10, p11);
            upk2(a[1][0], q00, q01); upk2(a[1][1], q10, q11);
            upk2(a[2][0], r00, r01); upk2(a[2][1], r10, r11);
            __half2 h0 = __floats2half2_rn(p00 + q00 + r00, p01 + q01 + r01);
            __half2 h1 = __floats2half2_rn(p10 + q10 + r10, p11 + q11 + r11);
            uint2 hv;
            hv.x = *(const uint32_t*)&h0;
            hv.y = *(const uint32_t*)&h1;
            hout[(size_t)n * 8 + hl] = hv;   // h[n][4hl..4hl+3]
        }
    }
}

// ====== G2: gather(h) -> zz[n,3,32], fused node-GEMM zz·W2flat -> out ======
// 4 lanes/node (8 nodes/warp-pass), 1x LDG.128/edge-lane (64B h rows).
template<int NWARP>
__global__ void __launch_bounds__(NWARP * 32)
g2_kernel(const int* __restrict__ row_ptr, const int* __restrict__ col_idx,
          const float2* __restrict__ p,
          const float* __restrict__ mu, const float* __restrict__ sigma,
          const uint4* __restrict__ h,      // [N][4] 16B chunks (64B rows)
          const float* __restrict__ W2,     // [3][32][16]
          float* __restrict__ out,          // [N][16] f32
          int n_nodes)
{
    constexpr int GRP = 8, CAP = GRP * 16;
    __shared__ float4 stg[NWARP][CAP];               // 16 KB
    __shared__ float  zz[NWARP][GRP][96];            // 24.6 KB
    __shared__ ull    wtab[16 * 49];                 // 6.3 KB (stride 49: cf-free)

    const int tid  = threadIdx.x;
    const int lane = tid & 31;
    const int wid  = tid >> 5;

    // Stage W2 pairs: wtab[o][q], q = k*16+fp -> (W2[k][2fp][o], W2[k][2fp+1][o])
    for (int i = tid; i < 16 * 48; i += NWARP * 32) {
        const int o = i / 48, q = i % 48;
        const int k = q / 16, fp = q % 16;
        wtab[o * 49 + q] = pk2(W2[((size_t)k * 32 + 2 * fp) * 16 + o],
                               (float)W2[((size_t)k * 32 + 2 * fp + 1) * 16 + o]);
    }
    __syncthreads();

    const int base = (blockIdx.x * NWARP + wid) * GRP;
    if (base >= n_nodes) return;

    LOAD_GAUSS_PARAMS();

    const int ng   = min(GRP, n_nodes - base);
    const int e0   = row_ptr[base];
    const int ecnt = row_ptr[base + ng] - e0;
    const bool fast = (ecnt <= CAP);

    if (fast) {
        for (int j = lane; j < ecnt; j += 32) {
            const int e = e0 + j;
            const int c = col_idx[e];
            const float2 pv = __ldg(p + e);
            float g0, g1, g2; GAUSS3(pv, g0, g1, g2);
            stg[wid][j] = make_float4(g0, g1, g2, __int_as_float(c));
        }
    }
    __syncwarp();

    // ---------------- gather phase: zz[n][k][8hl..8hl+7] ----------------
    {
        const int s  = lane >> 2;            // node slot 0..7 (all GRP at once)
        const int hl = lane & 3;             // 16B chunk of the 64B h row
        const int n = base + s;
        const bool valid = (n < n_nodes);
        const int nc  = valid ? n : base;
        const int st  = __ldg(row_ptr + nc);
        const int deg = valid ? (__ldg(row_ptr + nc + 1) - st) : 0;

        ull a[3][4];
        #pragma unroll
        for (int k = 0; k < 3; k++)
            #pragma unroll
            for (int v4 = 0; v4 < 4; v4++) a[k][v4] = 0ull;

        if (fast) {
            const float4* sd = &stg[wid][st - e0];
            const bool u16 = __all_sync(0xffffffffu, deg == 16);
            #define G2_BODY(J) do {                                           \
                const float4 ed = sd[(J)];                                    \
                const int c = __float_as_int(ed.w);                           \
                const uint4 v = __ldg(h + (size_t)c * 4 + hl);                \
                const float2 f0 = __half22float2(*(const __half2*)&v.x);      \
                const float2 f1 = __half22float2(*(const __half2*)&v.y);      \
                const float2 f2 = __half22float2(*(const __half2*)&v.z);      \
                const float2 f3 = __half22float2(*(const __half2*)&v.w);      \
                const ull hp0 = pk2(f0.x, f0.y);                              \
                const ull hp1 = pk2(f1.x, f1.y);                              \
                const ull hp2 = pk2(f2.x, f2.y);                              \
                const ull hp3 = pk2(f3.x, f3.y);                              \
                const ull w0 = pk2(ed.x, ed.x);                               \
                const ull w1 = pk2(ed.y, ed.y);                               \
                const ull w2 = pk2(ed.z, ed.z);                               \
                ffma2(a[0][0], w0, hp0); ffma2(a[0][1], w0, hp1);             \
                ffma2(a[0][2], w0, hp2); ffma2(a[0][3], w0, hp3);             \
                ffma2(a[1][0], w1, hp0); ffma2(a[1][1], w1, hp1);             \
                ffma2(a[1][2], w1, hp2); ffma2(a[1][3], w1, hp3);             \
                ffma2(a[2][0], w2, hp0); ffma2(a[2][1], w2, hp1);             \
                ffma2(a[2][2], w2, hp2); ffma2(a[2][3], w2, hp3);             \
            } while (0)
            if (u16) {
                #pragma unroll
                for (int j = 0; j < 16; j++) G2_BODY(j);
            } else {
                const int maxd = __reduce_max_sync(0xffffffffu, deg);
                for (int j = 0; j < maxd; j++)
                    if (j < deg) G2_BODY(j);
            }
            #undef G2_BODY
        } else {
            const int maxd = __reduce_max_sync(0xffffffffu, deg);
            for (int j = 0; j < maxd; j++) {
                if (j < deg) {
                    const int e = st + j;
                    const int c = __ldg(col_idx + e);
                    const float2 pv = __ldg(p + e);
                    float g0, g1, g2; GAUSS3(pv, g0, g1, g2);
                    const uint4 v = __ldg(h + (size_t)c * 4 + hl);
                    const float2 f0 = __half22float2(*(const __half2*)&v.x);
                    const float2 f1 = __half22float2(*(const __half2*)&v.y);
                    const float2 f2 = __half22float2(*(const __half2*)&v.z);
                    const float2 f3 = __half22float2(*(const __half2*)&v.w);
                    const ull hp0 = pk2(f0.x, f0.y);
                    const ull hp1 = pk2(f1.x, f1.y);
                    const ull hp2 = pk2(f2.x, f2.y);
                    const ull hp3 = pk2(f3.x, f3.y);
                    ffma2(a[0][0], pk2(g0, g0), hp0); ffma2(a[0][1], pk2(g0, g0), hp1);
                    ffma2(a[0][2], pk2(g0, g0), hp2); ffma2(a[0][3], pk2(g0, g0), hp3);
                    ffma2(a[1][0], pk2(g1, g1), hp0); ffma2(a[1][1], pk2(g1, g1), hp1);
                    ffma2(a[1][2], pk2(g1, g1), hp2); ffma2(a[1][3], pk2(g1, g1), hp3);
                    ffma2(a[2][0], pk2(g2, g2), hp0); ffma2(a[2][1], pk2(g2, g2), hp1);
                    ffma2(a[2][2], pk2(g2, g2), hp2); ffma2(a[2][3], pk2(g2, g2), hp3);
                }
            }
        }

        // zz[s][k*32 + 8hl .. +7] = a[k][0..3]
        #pragma unroll
        for (int k = 0; k < 3; k++) {
            ull* dst = (ull*)&zz[wid][s][k * 32 + 8 * hl];
            dst[0] = a[k][0]; dst[1] = a[k][1]; dst[2] = a[k][2]; dst[3] = a[k][3];
        }
    }
    __syncwarp();

    // ---------------- fused GEMM: out[n,o] = sum_q zzp[n][q] * wtab[o][q] ----
    {
        const int s2 = lane >> 4;            // node-slot parity
        const int o  = lane & 15;
        const ull* wcol = wtab + o * 49;

        ull acc[4];
        #pragma unroll
        for (int gg = 0; gg < 4; gg++) acc[gg] = 0ull;

        #pragma unroll
        for (int q = 0; q < 48; q++) {
            const ull w = wcol[q];
            #pragma unroll
            for (int gg = 0; gg < 4; gg++) {
                const ull z = *(const ull*)&zz[wid][gg * 2 + s2][2 * q];
                ffma2(acc[gg], z, w);
            }
        }

        #pragma unroll
        for (int gg = 0; gg < 4; gg++) {
            const int n = base + gg * 2 + s2;
            if (n < n_nodes) {
                float lo, hi; upk2(acc[gg], lo, hi);
                out[(size_t)n * 16 + o] = lo + hi;
            }
        }
    }
}

// =============================== launch ====================================
extern "C" void kernel_launch(void* const* d_in, const int* in_sizes, int n_in,
                              void* d_out, int out_size)
{
    const int*    row_ptr = (const int*)d_in[0];    // int32 (JAX x64 disabled)
    const int*    col_idx = (const int*)d_in[1];
    const float*  x       = (const float*)d_in[2];
    const float2* p       = (const float2*)d_in[3];
    const float*  mu      = (const float*)d_in[4];
    const float*  sg      = (const float*)d_in[5];
    const float*  W1      = (const float*)d_in[6];
    const float*  W2      = (const float*)d_in[7];

    const int n_nodes = in_sizes[0] - 1;

    void *y1p, *hp;
    cudaGetSymbolAddress(&y1p, g_y1);
    cudaGetSymbolAddress(&hp,  g_h);

    constexpr int NWARP = 8;
    constexpr int GRP   = 8;
    const int gblocks = (n_nodes + NWARP * GRP - 1) / (NWARP * GRP);
    const int tblocks = (n_nodes + 63) / 64;

    // T1: y1 = x * W1  (tensor cores, MT=64, coalesced epilogue)
    t1_mma_kernel<<<tblocks, 256>>>(x, W1, (uint4*)y1p, n_nodes);
    // G1H: h = gather(y1), stored fp16 64B rows
    g1h_kernel<NWARP, GRP><<<gblocks, NWARP * 32>>>(
        row_ptr, col_idx, p, mu, sg, (const uint2*)y1p,
        (uint2*)hp, n_nodes);
    // G2: zz = gather(h); out = zz * W2flat (fused node-GEMM)
    g2_kernel<NWARP><<<gblocks, NWARP * 32>>>(
        row_ptr, col_idx, p, mu, sg, (const uint4*)hp, W2,
        (float*)d_out, n_nodes);
}

// round 15
// speedup vs baseline: 1.0684x; 1.0684x over previous
#include <cuda_runtime.h>
#include <cuda_fp16.h>
#include <cstddef>
#include <cstdint>

// ---------------------------------------------------------------------------
// GMM (MoNet) graph conv — 3-kernel pipeline (round-12 structure):
//   T1:   y1 = x*W1 via mma.sync (fp16), MT=64, smem-aliased epilogue
//   G1T2: h[n] = gather(y1) (smem only), then per-node GEMM y2 = h*W2,
//         y2 stored as padded 128B rows [8 chunks][{k0,k1,k2,pad} half2]
//   G2:   out[n] = gather(y2), 1 LDG.128 per edge-lane (1 line/node)
// ---------------------------------------------------------------------------

#define MAXN 131072
__device__ __half g_y1[MAXN * 96];   // [N][3][32]  unpadded, 192B rows
__device__ __half g_y2[MAXN * 64];   // [N][8 chunks][8 halves], 128B rows

typedef unsigned long long ull;

__device__ __forceinline__ ull pk2(float x, float y) {
    ull r; asm("mov.b64 %0, {%1,%2};" : "=l"(r) : "f"(x), "f"(y)); return r;
}
__device__ __forceinline__ void upk2(ull v, float& x, float& y) {
    asm("mov.b64 {%0,%1}, %2;" : "=f"(x), "=f"(y) : "l"(v));
}
__device__ __forceinline__ void ffma2(ull& d, ull a, ull b) {
    asm("fma.rn.f32x2 %0, %1, %2, %0;" : "+l"(d) : "l"(a), "l"(b));
}

__device__ __forceinline__ void ldsm_x4(uint32_t& r0, uint32_t& r1,
                                        uint32_t& r2, uint32_t& r3, uint32_t a) {
    asm volatile("ldmatrix.sync.aligned.m8n8.x4.shared.b16 {%0,%1,%2,%3}, [%4];"
                 : "=r"(r0), "=r"(r1), "=r"(r2), "=r"(r3) : "r"(a));
}
__device__ __forceinline__ void ldsm_x2_t(uint32_t& r0, uint32_t& r1, uint32_t a) {
    asm volatile("ldmatrix.sync.aligned.m8n8.x2.trans.shared.b16 {%0,%1}, [%2];"
                 : "=r"(r0), "=r"(r1) : "r"(a));
}
__device__ __forceinline__ void mma16816(float* c,
    uint32_t a0, uint32_t a1, uint32_t a2, uint32_t a3, uint32_t b0, uint32_t b1) {
    asm volatile(
        "mma.sync.aligned.m16n8k16.row.col.f32.f16.f16.f32 "
        "{%0,%1,%2,%3}, {%4,%5,%6,%7}, {%8,%9}, {%0,%1,%2,%3};"
        : "+f"(c[0]), "+f"(c[1]), "+f"(c[2]), "+f"(c[3])
        : "r"(a0), "r"(a1), "r"(a2), "r"(a3), "r"(b0), "r"(b1));
}

// ======================= T1: tensor-core transform =========================
// CTA: 64 m-rows x 96 cols, K=64; Ys aliased over Xh/Wh -> 22.5KB smem,
// 6 CTA/SM (reg-bound), ~75% occ.
__global__ void __launch_bounds__(256)
t1_mma_kernel(const float* __restrict__ X, const float* __restrict__ W,
              uint4* __restrict__ Yg, int n_nodes)
{
    constexpr int MT   = 64;
    constexpr int XSTR = 72;    // halves/row (144B rows, 16B aligned)
    constexpr int WSTR = 104;   // halves/row (208B rows)
    constexpr int SSTR = 52;    // half2/row  (208B rows; g*20 mod 32 distinct)
    constexpr int SMEM_BYTES = MT * XSTR * 2 + 64 * WSTR * 2;   // 22528

    __shared__ __align__(16) char smem_raw[SMEM_BYTES];
    __half*  Xh = (__half*)smem_raw;
    __half*  Wh = (__half*)(smem_raw + MT * XSTR * 2);
    __half2* Ys = (__half2*)smem_raw;           // aliased: used after MMA loop

    const int tid = threadIdx.x;
    const int mt0 = blockIdx.x * MT;

    // Stage W1 -> Wh[f][k*32+h] fp16 (coalesced over j)
    for (int i = tid; i < 64 * 96; i += 256) {
        const int f = i / 96, j = i % 96;
        Wh[f * WSTR + j] = __float2half(W[((size_t)(j >> 5) * 64 + f) * 32 + (j & 31)]);
    }
    // Stage X -> Xh[m][f] fp16 via float4 loads (4 per thread, independent)
    #pragma unroll
    for (int k = 0; k < 4; k++) {
        const int i = tid + k * 256;               // < 1024
        const int m = i >> 4, f4 = i & 15;
        float4 v = make_float4(0.f, 0.f, 0.f, 0.f);
        if (mt0 + m < n_nodes)
            v = *(const float4*)(X + (size_t)(mt0 + m) * 64 + 4 * f4);
        uint2 hv;
        __half2 h0 = __floats2half2_rn(v.x, v.y);
        __half2 h1 = __floats2half2_rn(v.z, v.w);
        hv.x = *(const uint32_t*)&h0;
        hv.y = *(const uint32_t*)&h1;
        *(uint2*)&Xh[m * XSTR + 4 * f4] = hv;
    }
    __syncthreads();

    const int lane = tid & 31;
    const int wid  = tid >> 5;
    const int wm = wid >> 1;            // 0..3: rows 16*wm
    const int wn = wid & 1;             // 0..1: cols 48*wn
    const int g = lane >> 2, t = lane & 3;

    float acc[6][4];
    #pragma unroll
    for (int ni = 0; ni < 6; ni++)
        #pragma unroll
        for (int c = 0; c < 4; c++) acc[ni][c] = 0.f;

    const uint32_t xbase = (uint32_t)__cvta_generic_to_shared(Xh);
    const uint32_t wbase = (uint32_t)__cvta_generic_to_shared(Wh);
    const int arow  = wm * 16 + (lane & 15);
    const int acol8 = 8 * (lane >> 4);
    const int brow  = lane & 15;

    #pragma unroll
    for (int kt = 0; kt < 4; kt++) {
        const int k0 = kt * 16;
        uint32_t a0, a1, a2, a3;
        ldsm_x4(a0, a1, a2, a3, xbase + (arow * XSTR + k0 + acol8) * 2);
        #pragma unroll
        for (int ni = 0; ni < 6; ni++) {
            uint32_t b0, b1;
            ldsm_x2_t(b0, b1, wbase + ((k0 + brow) * WSTR + wn * 48 + ni * 8) * 2);
            mma16816(acc[ni], a0, a1, a2, a3, b0, b1);
        }
    }
    __syncthreads();   // all warps done reading Xh/Wh before Ys (aliased) writes

    // Epilogue: accs -> Ys (conflict-free), then coalesced uint4 copy to gmem.
    #pragma unroll
    for (int ni = 0; ni < 6; ni++) {
        const int cidx = wn * 24 + ni * 4 + t;
        Ys[(wm * 16 + g)     * SSTR + cidx] = __floats2half2_rn(acc[ni][0], acc[ni][1]);
        Ys[(wm * 16 + g + 8) * SSTR + cidx] = __floats2half2_rn(acc[ni][2], acc[ni][3]);
    }
    __syncthreads();

    const uint4* Ysv = (const uint4*)Ys;     // 13 uint4 per row (208B)
    #pragma unroll
    for (int k = 0; k < 3; k++) {
        const int i = tid + k * 256;         // < 768 = 64*12
        const int r = i / 12, c = i % 12;
        if (mt0 + r < n_nodes)
            Yg[(size_t)(mt0 + r) * 12 + c] = Ysv[r * 13 + c];
    }
}

// ============================== gaussians ==================================
#define LOAD_GAUSS_PARAMS()                                                   \
    const float m0_ = mu[0], m1_ = mu[1], m2_ = mu[2],                        \
                m3_ = mu[3], m4_ = mu[4], m5_ = mu[5];                        \
    float s_;                                                                 \
    s_ = sigma[0]; const float i0_ = 1.f/(s_*s_);                             \
    s_ = sigma[1]; const float i1_ = 1.f/(s_*s_);                             \
    s_ = sigma[2]; const float i2_ = 1.f/(s_*s_);                             \
    s_ = sigma[3]; const float i3_ = 1.f/(s_*s_);                             \
    s_ = sigma[4]; const float i4_ = 1.f/(s_*s_);                             \
    s_ = sigma[5]; const float i5_ = 1.f/(s_*s_);

#define GAUSS3(pv, g0, g1, g2) do {                                           \
    float dx_, dy_, q_;                                                       \
    dx_ = (pv).x - m0_; dy_ = (pv).y - m1_;                                   \
    q_ = dx_*dx_*i0_ + dy_*dy_*i1_; g0 = __expf(-0.5f * q_);                  \
    dx_ = (pv).x - m2_; dy_ = (pv).y - m3_;                                   \
    q_ = dx_*dx_*i2_ + dy_*dy_*i3_; g1 = __expf(-0.5f * q_);                  \
    dx_ = (pv).x - m4_; dy_ = (pv).y - m5_;                                   \
    q_ = dx_*dx_*i4_ + dy_*dy_*i5_; g2 = __expf(-0.5f * q_);                  \
} while (0)

// ============== G1 + T2 fused: gather -> h (smem) -> y2 = h*W2 =============
template<int NWARP, int GRP>
__global__ void __launch_bounds__(NWARP * 32)
g1t2_kernel(const int* __restrict__ row_ptr, const int* __restrict__ col_idx,
            const float2* __restrict__ p,
            const float* __restrict__ mu, const float* __restrict__ sigma,
            const uint2* __restrict__ y,      // y1: [N][24] uint2
            const float* __restrict__ W2,     // [3][32][16]
            unsigned* __restrict__ y2,        // [N][32] uint (128B rows)
            int n_nodes)
{
    constexpr int CAP = GRP * 16;
    __shared__ float4 stg[NWARP][CAP];
    __shared__ float  hbuf[NWARP][GRP][32];
    __shared__ ull    wp[24 * 33];            // W2 pairs, stride 33

    const int tid  = threadIdx.x;
    const int lane = tid & 31;
    const int wid  = tid >> 5;

    for (int i = tid; i < 24 * 32; i += NWARP * 32) {
        const int l = i / 32, f = i % 32;
        const int hp = l / 3, k = l % 3;
        const float* wrow = W2 + ((size_t)k * 32 + f) * 16 + 2 * hp;
        wp[l * 33 + f] = pk2(wrow[0], wrow[1]);
    }
    __syncthreads();

    const int base = (blockIdx.x * NWARP + wid) * GRP;
    if (base >= n_nodes) return;

    LOAD_GAUSS_PARAMS();

    const int ng   = min(GRP, n_nodes - base);
    const int e0   = row_ptr[base];
    const int ecnt = row_ptr[base + ng] - e0;
    const bool fast = (ecnt <= CAP);

    if (fast) {
        for (int j = lane; j < ecnt; j += 32) {
            const int e = e0 + j;
            const int c = col_idx[e];
            const float2 pv = __ldg(p + e);
            float g0, g1, g2; GAUSS3(pv, g0, g1, g2);
            stg[wid][j] = make_float4(g0, g1, g2, __int_as_float(c));
        }
    }
    __syncwarp();

    const int s  = lane >> 3;
    const int hl = lane & 7;

    #pragma unroll
    for (int pi = 0; pi < GRP / 4; pi++) {
        const int n = base + pi * 4 + s;
        const bool valid = (n < n_nodes);
        const int nc  = valid ? n : base;
        const int st  = __ldg(row_ptr + nc);
        const int deg = valid ? (__ldg(row_ptr + nc + 1) - st) : 0;

        ull a[3][2];
        #pragma unroll
        for (int k = 0; k < 3; k++) { a[k][0] = 0ull; a[k][1] = 0ull; }

        if (fast) {
            const float4* sd = &stg[wid][st - e0];
            const bool u16 = __all_sync(0xffffffffu, deg == 16);
            #define G1_BODY(J) do {                                           \
                const float4 ed = sd[(J)];                                    \
                const int c = __float_as_int(ed.w);                           \
                const uint2* yr = y + (size_t)c * 24 + hl;                    \
                const uint2 v0 = __ldg(yr);                                   \
                const uint2 v1 = __ldg(yr + 8);                               \
                const uint2 v2 = __ldg(yr + 16);                              \
                const float2 c00 = __half22float2(*(const __half2*)&v0.x);    \
                const float2 c01 = __half22float2(*(const __half2*)&v0.y);    \
                const float2 c10 = __half22float2(*(const __half2*)&v1.x);    \
                const float2 c11 = __half22float2(*(const __half2*)&v1.y);    \
                const float2 c20 = __half22float2(*(const __half2*)&v2.x);    \
                const float2 c21 = __half22float2(*(const __half2*)&v2.y);    \
                const ull w0 = pk2(ed.x, ed.x);                               \
                const ull w1 = pk2(ed.y, ed.y);                               \
                const ull w2 = pk2(ed.z, ed.z);                               \
                ffma2(a[0][0], w0, pk2(c00.x, c00.y));                        \
                ffma2(a[0][1], w0, pk2(c01.x, c01.y));                        \
                ffma2(a[1][0], w1, pk2(c10.x, c10.y));                        \
                ffma2(a[1][1], w1, pk2(c11.x, c11.y));                        \
                ffma2(a[2][0], w2, pk2(c20.x, c20.y));                        \
                ffma2(a[2][1], w2, pk2(c21.x, c21.y));                        \
            } while (0)
            if (u16) {
                #pragma unroll
                for (int j = 0; j < 16; j++) G1_BODY(j);
            } else {
                const int maxd = __reduce_max_sync(0xffffffffu, deg);
                for (int j = 0; j < maxd; j++)
                    if (j < deg) G1_BODY(j);
            }
            #undef G1_BODY
        } else {
            const int maxd = __reduce_max_sync(0xffffffffu, deg);
            for (int j = 0; j < maxd; j++) {
                if (j < deg) {
                    const int e = st + j;
                    const int c = __ldg(col_idx + e);
                    const float2 pv = __ldg(p + e);
                    float g0, g1, g2; GAUSS3(pv, g0, g1, g2);
                    const uint2* yr = y + (size_t)c * 24 + hl;
                    const uint2 v0 = __ldg(yr);
                    const uint2 v1 = __ldg(yr + 8);
                    const uint2 v2 = __ldg(yr + 16);
                    const float2 c00 = __half22float2(*(const __half2*)&v0.x);
                    const float2 c01 = __half22float2(*(const __half2*)&v0.y);
                    const float2 c10 = __half22float2(*(const __half2*)&v1.x);
                    const float2 c11 = __half22float2(*(const __half2*)&v1.y);
                    const float2 c20 = __half22float2(*(const __half2*)&v2.x);
                    const float2 c21 = __half22float2(*(const __half2*)&v2.y);
                    ffma2(a[0][0], pk2(g0, g0), pk2(c00.x, c00.y));
                    ffma2(a[0][1], pk2(g0, g0), pk2(c01.x, c01.y));
                    ffma2(a[1][0], pk2(g1, g1), pk2(c10.x, c10.y));
                    ffma2(a[1][1], pk2(g1, g1), pk2(c11.x, c11.y));
                    ffma2(a[2][0], pk2(g2, g2), pk2(c20.x, c20.y));
                    ffma2(a[2][1], pk2(g2, g2), pk2(c21.x, c21.y));
                }
            }
        }

        float p00, p01, p10, p11, q00, q01, q10, q11, r00, r01, r10, r11;
        upk2(a[0][0], p00, p01); upk2(a[0][1], p10, p11);
        upk2(a[1][0], q00, q01); upk2(a[1][1], q10, q11);
        upk2(a[2][0], r00, r01); upk2(a[2][1], r10, r11);
        float4 o;
        o.x = p00 + q00 + r00;
        o.y = p01 + q01 + r01;
        o.z = p10 + q10 + r10;
        o.w = p11 + q11 + r11;
        *(float4*)&hbuf[wid][pi * 4 + s][4 * hl] = o;
    }
    __syncwarp();

    // fused T2: y2[g] = h[g] * W2
    const int wl = (lane < 24) ? lane : 0;
    const ull* wcol = wp + wl * 33;

    ull acc[GRP];
    #pragma unroll
    for (int g = 0; g < GRP; g++) acc[g] = 0ull;

    #pragma unroll
    for (int fc = 0; fc < 8; fc++) {
        ull wr[4];
        #pragma unroll
        for (int f4 = 0; f4 < 4; f4++) wr[f4] = wcol[fc * 4 + f4];
        #pragma unroll
        for (int g = 0; g < GRP; g++) {
            const float4 hv = *(const float4*)&hbuf[wid][g][fc * 4];
            ffma2(acc[g], pk2(hv.x, hv.x), wr[0]);
            ffma2(acc[g], pk2(hv.y, hv.y), wr[1]);
            ffma2(acc[g], pk2(hv.z, hv.z), wr[2]);
            ffma2(acc[g], pk2(hv.w, hv.w), wr[3]);
        }
    }

    const int oidx = (lane / 3) * 4 + (lane % 3);
    #pragma unroll
    for (int g = 0; g < GRP; g++) {
        const int n = base + g;
        if (lane < 24 && n < n_nodes) {
            float lo, hi; upk2(acc[g], lo, hi);
            const __half2 hv = __floats2half2_rn(lo, hi);
            y2[(size_t)n * 32 + oidx] = *(const unsigned*)&hv;
        }
    }
}

// ---- G2: H=16, padded 128B rows; 8 lanes/node, 1x LDG.128 per edge --------
template<int NWARP, int GRP>
__global__ void __launch_bounds__(NWARP * 32)
gather_h16(const int* __restrict__ row_ptr, const int* __restrict__ col_idx,
           const float2* __restrict__ p,
           const float* __restrict__ mu, const float* __restrict__ sigma,
           const uint4* __restrict__ y,     // [N][8] 16B chunks
           float* __restrict__ out,         // [N][16] f32
           int n_nodes)
{
    constexpr int CAP = GRP * 16;
    __shared__ float4 stg[NWARP][CAP];

    const int lane = threadIdx.x & 31;
    const int wid  = threadIdx.x >> 5;
    const int s    = lane >> 3;
    const int hl   = lane & 7;
    const int base = (blockIdx.x * NWARP + wid) * GRP;
    if (base >= n_nodes) return;

    LOAD_GAUSS_PARAMS();

    const int ng   = min(GRP, n_nodes - base);
    const int e0   = row_ptr[base];
    const int ecnt = row_ptr[base + ng] - e0;
    const bool fast = (ecnt <= CAP);

    if (fast) {
        for (int j = lane; j < ecnt; j += 32) {
            const int e = e0 + j;
            const int c = col_idx[e];
            const float2 pv = __ldg(p + e);
            float g0, g1, g2; GAUSS3(pv, g0, g1, g2);
            stg[wid][j] = make_float4(g0, g1, g2, __int_as_float(c));
        }
    }
    __syncwarp();

    #pragma unroll
    for (int pi = 0; pi < GRP / 4; pi++) {
        const int n = base + pi * 4 + s;
        const bool valid = (n < n_nodes);
        const int nc  = valid ? n : base;
        const int st  = __ldg(row_ptr + nc);
        const int deg = valid ? (__ldg(row_ptr + nc + 1) - st) : 0;

        ull a0 = 0ull, a1 = 0ull, a2 = 0ull;

        if (fast) {
            const float4* sd = &stg[wid][st - e0];
            const bool u16 = __all_sync(0xffffffffu, deg == 16);
            #define G2_BODY(J) do {                                           \
                const float4 ed = sd[(J)];                                    \
                const int c = __float_as_int(ed.w);                           \
                const uint4 v = __ldg(y + (size_t)c * 8 + hl);                \
                const float2 f0 = __half22float2(*(const __half2*)&v.x);      \
                const float2 f1 = __half22float2(*(const __half2*)&v.y);      \
                const float2 f2 = __half22float2(*(const __half2*)&v.z);      \
                ffma2(a0, pk2(ed.x, ed.x), pk2(f0.x, f0.y));                  \
                ffma2(a1, pk2(ed.y, ed.y), pk2(f1.x, f1.y));                  \
                ffma2(a2, pk2(ed.z, ed.z), pk2(f2.x, f2.y));                  \
            } while (0)
            if (u16) {
                #pragma unroll
                for (int j = 0; j < 16; j++) G2_BODY(j);
            } else {
                const int maxd = __reduce_max_sync(0xffffffffu, deg);
                for (int j = 0; j < maxd; j++)
                    if (j < deg) G2_BODY(j);
            }
            #undef G2_BODY
        } else {
            const int maxd = __reduce_max_sync(0xffffffffu, deg);
            for (int j = 0; j < maxd; j++) {
                if (j < deg) {
                    const int e = st + j;
                    const int c = __ldg(col_idx + e);
                    const float2 pv = __ldg(p + e);
                    float g0, g1, g2; GAUSS3(pv, g0, g1, g2);
                    const uint4 v = __ldg(y + (size_t)c * 8 + hl);
                    const float2 f0 = __half22float2(*(const __half2*)&v.x);
                    const float2 f1 = __half22float2(*(const __half2*)&v.y);
                    const float2 f2 = __half22float2(*(const __half2*)&v.z);
                    ffma2(a0, pk2(g0, g0), pk2(f0.x, f0.y));
                    ffma2(a1, pk2(g1, g1), pk2(f1.x, f1.y));
                    ffma2(a2, pk2(g2, g2), pk2(f2.x, f2.y));
                }
            }
        }

        if (valid) {
            float x0, x1, y0v, y1v, z0, z1;
            upk2(a0, x0, x1); upk2(a1, y0v, y1v); upk2(a2, z0, z1);
            float2 o = make_float2(x0 + y0v + z0, x1 + y1v + z1);
            *(float2*)(out + (size_t)n * 16 + 2 * hl) = o;
        }
    }
}

// =============================== launch ====================================
extern "C" void kernel_launch(void* const* d_in, const int* in_sizes, int n_in,
                              void* d_out, int out_size)
{
    const int*    row_ptr = (const int*)d_in[0];    // int32 (JAX x64 disabled)
    const int*    col_idx = (const int*)d_in[1];
    const float*  x       = (const float*)d_in[2];
    const float2* p       = (const float2*)d_in[3];
    const float*  mu      = (const float*)d_in[4];
    const float*  sg      = (const float*)d_in[5];
    const float*  W1      = (const float*)d_in[6];
    const float*  W2      = (const float*)d_in[7];

    const int n_nodes = in_sizes[0] - 1;

    void *y1p, *y2p;
    cudaGetSymbolAddress(&y1p, g_y1);
    cudaGetSymbolAddress(&y2p, g_y2);

    constexpr int NWARP = 8;
    constexpr int GRP   = 8;
    const int gblocks = (n_nodes + NWARP * GRP - 1) / (NWARP * GRP);
    const int tblocks = (n_nodes + 63) / 64;

    // T1: y1 = x * W1  (tensor cores, MT=64, aliased-smem epilogue)
    t1_mma_kernel<<<tblocks, 256>>>(x, W1, (uint4*)y1p, n_nodes);
    // G1+T2: h = gather(y1) in smem; y2 = h*W2 (padded 128B rows)
    g1t2_kernel<NWARP, GRP><<<gblocks, NWARP * 32>>>(
        row_ptr, col_idx, p, mu, sg, (const uint2*)y1p, W2,
        (unsigned*)y2p, n_nodes);
    // G2: out = gather(y2)  (8 lanes/node, 1x LDG.128/edge)
    gather_h16<NWARP, GRP><<<gblocks, NWARP * 32>>>(
        row_ptr, col_idx, p, mu, sg, (const uint4*)y2p, (float*)d_out, n_nodes);
}

// round 16
// speedup vs baseline: 1.2291x; 1.1505x over previous
#include <cuda_runtime.h>
#include <cuda_fp16.h>
#include <cstddef>
#include <cstdint>

// ---------------------------------------------------------------------------
// GMM (MoNet) graph conv — 3-kernel pipeline:
//   XCVT:  xh = fp16(x)  [N][64] halves (128B rows)
//   FUSED: per 64-node block: zz[n,3,64] = gather(xh) (1 LDG.128/edge-lane),
//          mma1: h = zz * W1stack (tensor cores, K=192),
//          mma2: y2 = h * W2cols (tensor cores, K=32) -> padded 128B rows
//   G2:    out[n] = gather(y2), 1 LDG.128 per edge-lane (unchanged, proven)
// ---------------------------------------------------------------------------

#define MAXN 131072
__device__ __half g_xh[MAXN * 64];   // x fp16: [N][64] halves, 128B rows
__device__ __half g_y2[MAXN * 64];   // [N][8 chunks][{k0,k1,k2,pad} half2], 128B rows

typedef unsigned long long ull;

__device__ __forceinline__ ull pk2(float x, float y) {
    ull r; asm("mov.b64 %0, {%1,%2};" : "=l"(r) : "f"(x), "f"(y)); return r;
}
__device__ __forceinline__ void upk2(ull v, float& x, float& y) {
    asm("mov.b64 {%0,%1}, %2;" : "=f"(x), "=f"(y) : "l"(v));
}
__device__ __forceinline__ void ffma2(ull& d, ull a, ull b) {
    asm("fma.rn.f32x2 %0, %1, %2, %0;" : "+l"(d) : "l"(a), "l"(b));
}

__device__ __forceinline__ void ldsm_x4(uint32_t& r0, uint32_t& r1,
                                        uint32_t& r2, uint32_t& r3, uint32_t a) {
    asm volatile("ldmatrix.sync.aligned.m8n8.x4.shared.b16 {%0,%1,%2,%3}, [%4];"
                 : "=r"(r0), "=r"(r1), "=r"(r2), "=r"(r3) : "r"(a));
}
__device__ __forceinline__ void ldsm_x2_t(uint32_t& r0, uint32_t& r1, uint32_t a) {
    asm volatile("ldmatrix.sync.aligned.m8n8.x2.trans.shared.b16 {%0,%1}, [%2];"
                 : "=r"(r0), "=r"(r1) : "r"(a));
}
__device__ __forceinline__ void mma16816(float* c,
    uint32_t a0, uint32_t a1, uint32_t a2, uint32_t a3, uint32_t b0, uint32_t b1) {
    asm volatile(
        "mma.sync.aligned.m16n8k16.row.col.f32.f16.f16.f32 "
        "{%0,%1,%2,%3}, {%4,%5,%6,%7}, {%8,%9}, {%0,%1,%2,%3};"
        : "+f"(c[0]), "+f"(c[1]), "+f"(c[2]), "+f"(c[3])
        : "r"(a0), "r"(a1), "r"(a2), "r"(a3), "r"(b0), "r"(b1));
}

// ============================== gaussians ==================================
#define LOAD_GAUSS_PARAMS()                                                   \
    const float m0_ = mu[0], m1_ = mu[1], m2_ = mu[2],                        \
                m3_ = mu[3], m4_ = mu[4], m5_ = mu[5];                        \
    float s_;                                                                 \
    s_ = sigma[0]; const float i0_ = 1.f/(s_*s_);                             \
    s_ = sigma[1]; const float i1_ = 1.f/(s_*s_);                             \
    s_ = sigma[2]; const float i2_ = 1.f/(s_*s_);                             \
    s_ = sigma[3]; const float i3_ = 1.f/(s_*s_);                             \
    s_ = sigma[4]; const float i4_ = 1.f/(s_*s_);                             \
    s_ = sigma[5]; const float i5_ = 1.f/(s_*s_);

#define GAUSS3(pv, g0, g1, g2) do {                                           \
    float dx_, dy_, q_;                                                       \
    dx_ = (pv).x - m0_; dy_ = (pv).y - m1_;                                   \
    q_ = dx_*dx_*i0_ + dy_*dy_*i1_; g0 = __expf(-0.5f * q_);                  \
    dx_ = (pv).x - m2_; dy_ = (pv).y - m3_;                                   \
    q_ = dx_*dx_*i2_ + dy_*dy_*i3_; g1 = __expf(-0.5f * q_);                  \
    dx_ = (pv).x - m4_; dy_ = (pv).y - m5_;                                   \
    q_ = dx_*dx_*i4_ + dy_*dy_*i5_; g2 = __expf(-0.5f * q_);                  \
} while (0)

// ======================= XCVT: x -> fp16 ===================================
__global__ void xcvt_kernel(const float4* __restrict__ X, uint2* __restrict__ Xh,
                            int n4)
{
    const int i = blockIdx.x * 256 + threadIdx.x;
    if (i < n4) {
        const float4 v = X[i];
        __half2 h0 = __floats2half2_rn(v.x, v.y);
        __half2 h1 = __floats2half2_rn(v.z, v.w);
        uint2 o;
        o.x = *(const uint32_t*)&h0;
        o.y = *(const uint32_t*)&h1;
        Xh[i] = o;
    }
}

// ============ FUSED: gather(xh) -> zz -> mma1 -> h -> mma2 -> y2 ===========
// 256 thr (8 warps), 64 nodes/CTA (8 per warp). Dynamic smem 50688B:
//   [0:16384)      stg[8][128] float4  (phase 1) / Wb1[192][40] half (phase 3+)
//   [16384:41984)  Az[64][200] half    (zz, fp16 A matrix)
//   [41984:45568)  Wb2[32][56] half
//   [45568:50688)  hs[64][40] half
__global__ void __launch_bounds__(256)
fused_l1_kernel(const int* __restrict__ row_ptr, const int* __restrict__ col_idx,
                const float2* __restrict__ p,
                const float* __restrict__ mu, const float* __restrict__ sigma,
                const uint4* __restrict__ xh,   // [N][8] 16B chunks (128B rows)
                const float* __restrict__ W1,   // [3][64][32] = [192][32]
                const float* __restrict__ W2,   // [3][32][16]
                unsigned* __restrict__ y2,      // [N][32] uint (128B rows)
                int n_nodes)
{
    constexpr int ASTR = 200;   // halves/row of Az (400B, 16B-aligned stores)
    constexpr int W1S  = 40;    // halves/row of Wb1
    constexpr int W2S  = 56;    // halves/row of Wb2
    constexpr int HSS  = 40;    // halves/row of hs

    extern __shared__ __align__(16) char dsm[];
    float4 (*stg)[128] = (float4 (*)[128])dsm;
    __half* Wb1 = (__half*)dsm;
    __half* Az  = (__half*)(dsm + 16384);
    __half* Wb2 = (__half*)(dsm + 41984);
    __half* hs  = (__half*)(dsm + 45568);

    const int tid  = threadIdx.x;
    const int lane = tid & 31;
    const int wid  = tid >> 5;
    const int blk0 = blockIdx.x * 64;        // first node of this CTA
    const int base = blk0 + wid * 8;         // this warp's 8 nodes

    LOAD_GAUSS_PARAMS();

    // ---------------- phase 1: stage edge gaussians ----------------
    {
        const int b0  = min(base, n_nodes);
        const int ng  = max(0, min(8, n_nodes - base));
        const int e0  = row_ptr[b0];
        const int ecnt = (ng > 0) ? (row_ptr[b0 + ng] - e0) : 0;
        const bool fast = (ecnt <= 128);

        if (fast) {
            for (int j = lane; j < ecnt; j += 32) {
                const int e = e0 + j;
                const int c = col_idx[e];
                const float2 pv = __ldg(p + e);
                float g0, g1, g2; GAUSS3(pv, g0, g1, g2);
                stg[wid][j] = make_float4(g0, g1, g2, __int_as_float(c));
            }
        }
        __syncwarp();

        // ---------------- phase 2: gather -> Az fp16 ----------------
        const int s  = lane >> 3;            // node slot (4 per pass)
        const int hl = lane & 7;             // 16B chunk of the 128B x row

        #pragma unroll
        for (int pi = 0; pi < 2; pi++) {
            const int local = wid * 8 + pi * 4 + s;
            const int n = blk0 + local;
            const bool valid = (n < n_nodes);
            const int nc  = valid ? n : b0;
            const int st  = __ldg(row_ptr + nc);
            const int deg = valid ? (__ldg(row_ptr + nc + 1) - st) : 0;

            ull a[3][4];
            #pragma unroll
            for (int k = 0; k < 3; k++)
                #pragma unroll
                for (int v4 = 0; v4 < 4; v4++) a[k][v4] = 0ull;

            if (fast) {
                const float4* sd = &stg[wid][st - e0];
                const bool u16 = __all_sync(0xffffffffu, deg == 16);
                #define F_BODY(J) do {                                        \
                    const float4 ed = sd[(J)];                                \
                    const int c = __float_as_int(ed.w);                       \
                    const uint4 v = __ldg(xh + (size_t)c * 8 + hl);           \
                    const float2 f0 = __half22float2(*(const __half2*)&v.x);  \
                    const float2 f1 = __half22float2(*(const __half2*)&v.y);  \
                    const float2 f2 = __half22float2(*(const __half2*)&v.z);  \
                    const float2 f3 = __half22float2(*(const __half2*)&v.w);  \
                    const ull hp0 = pk2(f0.x, f0.y);                          \
                    const ull hp1 = pk2(f1.x, f1.y);                          \
                    const ull hp2 = pk2(f2.x, f2.y);                          \
                    const ull hp3 = pk2(f3.x, f3.y);                          \
                    const ull w0 = pk2(ed.x, ed.x);                           \
                    const ull w1 = pk2(ed.y, ed.y);                           \
                    const ull w2 = pk2(ed.z, ed.z);                           \
                    ffma2(a[0][0], w0, hp0); ffma2(a[0][1], w0, hp1);         \
                    ffma2(a[0][2], w0, hp2); ffma2(a[0][3], w0, hp3);         \
                    ffma2(a[1][0], w1, hp0); ffma2(a[1][1], w1, hp1);         \
                    ffma2(a[1][2], w1, hp2); ffma2(a[1][3], w1, hp3);         \
                    ffma2(a[2][0], w2, hp0); ffma2(a[2][1], w2, hp1);         \
                    ffma2(a[2][2], w2, hp2); ffma2(a[2][3], w2, hp3);         \
                } while (0)
                if (u16) {
                    #pragma unroll
                    for (int j = 0; j < 16; j++) F_BODY(j);
                } else {
                    const int maxd = __reduce_max_sync(0xffffffffu, deg);
                    for (int j = 0; j < maxd; j++)
                        if (j < deg) F_BODY(j);
                }
                #undef F_BODY
            } else {
                const int maxd = __reduce_max_sync(0xffffffffu, deg);
                for (int j = 0; j < maxd; j++) {
                    if (j < deg) {
                        const int e = st + j;
                        const int c = __ldg(col_idx + e);
                        const float2 pv = __ldg(p + e);
                        float g0, g1, g2; GAUSS3(pv, g0, g1, g2);
                        const uint4 v = __ldg(xh + (size_t)c * 8 + hl);
                        const float2 f0 = __half22float2(*(const __half2*)&v.x);
                        const float2 f1 = __half22float2(*(const __half2*)&v.y);
                        const float2 f2 = __half22float2(*(const __half2*)&v.z);
                        const float2 f3 = __half22float2(*(const __half2*)&v.w);
                        const ull hp0 = pk2(f0.x, f0.y);
                        const ull hp1 = pk2(f1.x, f1.y);
                        const ull hp2 = pk2(f2.x, f2.y);
                        const ull hp3 = pk2(f3.x, f3.y);
                        ffma2(a[0][0], pk2(g0, g0), hp0); ffma2(a[0][1], pk2(g0, g0), hp1);
                        ffma2(a[0][2], pk2(g0, g0), hp2); ffma2(a[0][3], pk2(g0, g0), hp3);
                        ffma2(a[1][0], pk2(g1, g1), hp0); ffma2(a[1][1], pk2(g1, g1), hp1);
                        ffma2(a[1][2], pk2(g1, g1), hp2); ffma2(a[1][3], pk2(g1, g1), hp3);
                        ffma2(a[2][0], pk2(g2, g2), hp0); ffma2(a[2][1], pk2(g2, g2), hp1);
                        ffma2(a[2][2], pk2(g2, g2), hp2); ffma2(a[2][3], pk2(g2, g2), hp3);
                    }
                }
            }

            // Az[local][k*64 + 8hl .. +7] (fp16) — one STS.128 per k
            #pragma unroll
            for (int k = 0; k < 3; k++) {
                __half2 hh[4];
                #pragma unroll
                for (int v4 = 0; v4 < 4; v4++) {
                    float lo, hi; upk2(a[k][v4], lo, hi);
                    hh[v4] = __floats2half2_rn(lo, hi);
                }
                *(uint4*)&Az[local * ASTR + k * 64 + 8 * hl] = *(const uint4*)hh;
            }
        }
    }
    __syncthreads();   // gather done everywhere; stg region now dead

    // ---------------- phase 3: stage W1 (over stg) + W2 ----------------
    for (int i = tid; i < 192 * 32; i += 256) {
        const int q = i >> 5, h = i & 31;          // Wb1[q][h] = W1[q*32+h]
        Wb1[q * W1S + h] = __float2half(W1[i]);
    }
    for (int i = tid; i < 32 * 48; i += 256) {
        const int f = i / 48, o = i % 48;          // o = k*16 + h
        const int k = o >> 4, hh = o & 15;
        Wb2[f * W2S + o] = __float2half(W2[((size_t)k * 32 + f) * 16 + hh]);
    }
    __syncthreads();

    // ---------------- phase 4: mma1  h[64x32] = Az[64x192] * Wb1 ----------
    const int wm = wid >> 1;            // 0..3: rows 16*wm
    const int wn = wid & 1;             // 0..1: cols 16*wn (mma1) / 24*wn (mma2)
    const int g = lane >> 2, t = lane & 3;
    const uint32_t abase  = (uint32_t)__cvta_generic_to_shared(Az);
    const uint32_t w1base = (uint32_t)__cvta_generic_to_shared(Wb1);
    const uint32_t w2base = (uint32_t)__cvta_generic_to_shared(Wb2);
    const uint32_t hbase  = (uint32_t)__cvta_generic_to_shared(hs);
    const int arow  = wm * 16 + (lane & 15);
    const int acol8 = 8 * (lane >> 4);
    const int brow  = lane & 15;

    {
        float acc[2][4];
        #pragma unroll
        for (int ni = 0; ni < 2; ni++)
            #pragma unroll
            for (int c = 0; c < 4; c++) acc[ni][c] = 0.f;

        #pragma unroll
        for (int kt = 0; kt < 12; kt++) {
            const int k0 = kt * 16;
            uint32_t a0, a1, a2, a3;
            ldsm_x4(a0, a1, a2, a3, abase + (arow * ASTR + k0 + acol8) * 2);
            #pragma unroll
            for (int ni = 0; ni < 2; ni++) {
                uint32_t b0, b1;
                ldsm_x2_t(b0, b1, w1base + ((k0 + brow) * W1S + wn * 16 + ni * 8) * 2);
                mma16816(acc[ni], a0, a1, a2, a3, b0, b1);
            }
        }
        // h -> hs fp16
        #pragma unroll
        for (int ni = 0; ni < 2; ni++) {
            const int col = wn * 16 + ni * 8 + 2 * t;
            *(__half2*)&hs[(wm * 16 + g)     * HSS + col] = __floats2half2_rn(acc[ni][0], acc[ni][1]);
            *(__half2*)&hs[(wm * 16 + g + 8) * HSS + col] = __floats2half2_rn(acc[ni][2], acc[ni][3]);
        }
    }
    __syncthreads();

    // ---------------- phase 5: mma2  y2[64x48] = hs[64x32] * Wb2 ----------
    {
        float acc[3][4];
        #pragma unroll
        for (int ni = 0; ni < 3; ni++)
            #pragma unroll
            for (int c = 0; c < 4; c++) acc[ni][c] = 0.f;

        #pragma unroll
        for (int kt = 0; kt < 2; kt++) {
            const int k0 = kt * 16;
            uint32_t a0, a1, a2, a3;
            ldsm_x4(a0, a1, a2, a3, hbase + (arow * HSS + k0 + acol8) * 2);
            #pragma unroll
            for (int ni = 0; ni < 3; ni++) {
                uint32_t b0, b1;
                ldsm_x2_t(b0, b1, w2base + ((k0 + brow) * W2S + wn * 24 + ni * 8) * 2);
                mma16816(acc[ni], a0, a1, a2, a3, b0, b1);
            }
        }

        // y2 write: o = k*16 + h; element = half2 (h even pair), idx = (h/2)*4 + k
        #pragma unroll
        for (int ni = 0; ni < 3; ni++) {
            const int o0 = wn * 24 + ni * 8 + 2 * t;
            const int k  = o0 >> 4;
            const int hh = o0 & 15;
            const int idx = (hh >> 1) * 4 + k;
            const int n0 = blk0 + wm * 16 + g;
            if (n0 < n_nodes) {
                const __half2 hv = __floats2half2_rn(acc[ni][0], acc[ni][1]);
                y2[(size_t)n0 * 32 + idx] = *(const unsigned*)&hv;
            }
            if (n0 + 8 < n_nodes) {
                const __half2 hv = __floats2half2_rn(acc[ni][2], acc[ni][3]);
                y2[(size_t)(n0 + 8) * 32 + idx] = *(const unsigned*)&hv;
            }
        }
    }
}

// ---- G2: H=16, padded 128B rows; 8 lanes/node, 1x LDG.128 per edge --------
template<int NWARP, int GRP>
__global__ void __launch_bounds__(NWARP * 32)
gather_h16(const int* __restrict__ row_ptr, const int* __restrict__ col_idx,
           const float2* __restrict__ p,
           const float* __restrict__ mu, const float* __restrict__ sigma,
           const uint4* __restrict__ y,     // [N][8] 16B chunks
           float* __restrict__ out,         // [N][16] f32
           int n_nodes)
{
    constexpr int CAP = GRP * 16;
    __shared__ float4 stg[NWARP][CAP];

    const int lane = threadIdx.x & 31;
    const int wid  = threadIdx.x >> 5;
    const int s    = lane >> 3;
    const int hl   = lane & 7;
    const int base = (blockIdx.x * NWARP + wid) * GRP;
    if (base >= n_nodes) return;

    LOAD_GAUSS_PARAMS();

    const int ng   = min(GRP, n_nodes - base);
    const int e0   = row_ptr[base];
    const int ecnt = row_ptr[base + ng] - e0;
    const bool fast = (ecnt <= CAP);

    if (fast) {
        for (int j = lane; j < ecnt; j += 32) {
            const int e = e0 + j;
            const int c = col_idx[e];
            const float2 pv = __ldg(p + e);
            float g0, g1, g2; GAUSS3(pv, g0, g1, g2);
            stg[wid][j] = make_float4(g0, g1, g2, __int_as_float(c));
        }
    }
    __syncwarp();

    #pragma unroll
    for (int pi = 0; pi < GRP / 4; pi++) {
        const int n = base + pi * 4 + s;
        const bool valid = (n < n_nodes);
        const int nc  = valid ? n : base;
        const int st  = __ldg(row_ptr + nc);
        const int deg = valid ? (__ldg(row_ptr + nc + 1) - st) : 0;

        ull a0 = 0ull, a1 = 0ull, a2 = 0ull;

        if (fast) {
            const float4* sd = &stg[wid][st - e0];
            const bool u16 = __all_sync(0xffffffffu, deg == 16);
            #define G2_BODY(J) do {                                           \
                const float4 ed = sd[(J)];                                    \
                const int c = __float_as_int(ed.w);                           \
                const uint4 v = __ldg(y + (size_t)c * 8 + hl);                \
                const float2 f0 = __half22float2(*(const __half2*)&v.x);      \
                const float2 f1 = __half22float2(*(const __half2*)&v.y);      \
                const float2 f2 = __half22float2(*(const __half2*)&v.z);      \
                ffma2(a0, pk2(ed.x, ed.x), pk2(f0.x, f0.y));                  \
                ffma2(a1, pk2(ed.y, ed.y), pk2(f1.x, f1.y));                  \
                ffma2(a2, pk2(ed.z, ed.z), pk2(f2.x, f2.y));                  \
            } while (0)
            if (u16) {
                #pragma unroll
                for (int j = 0; j < 16; j++) G2_BODY(j);
            } else {
                const int maxd = __reduce_max_sync(0xffffffffu, deg);
                for (int j = 0; j < maxd; j++)
                    if (j < deg) G2_BODY(j);
            }
            #undef G2_BODY
        } else {
            const int maxd = __reduce_max_sync(0xffffffffu, deg);
            for (int j = 0; j < maxd; j++) {
                if (j < deg) {
                    const int e = st + j;
                    const int c = __ldg(col_idx + e);
                    const float2 pv = __ldg(p + e);
                    float g0, g1, g2; GAUSS3(pv, g0, g1, g2);
                    const uint4 v = __ldg(y + (size_t)c * 8 + hl);
                    const float2 f0 = __half22float2(*(const __half2*)&v.x);
                    const float2 f1 = __half22float2(*(const __half2*)&v.y);
                    const float2 f2 = __half22float2(*(const __half2*)&v.z);
                    ffma2(a0, pk2(g0, g0), pk2(f0.x, f0.y));
                    ffma2(a1, pk2(g1, g1), pk2(f1.x, f1.y));
                    ffma2(a2, pk2(g2, g2), pk2(f2.x, f2.y));
                }
            }
        }

        if (valid) {
            float x0, x1, y0v, y1v, z0, z1;
            upk2(a0, x0, x1); upk2(a1, y0v, y1v); upk2(a2, z0, z1);
            float2 o = make_float2(x0 + y0v + z0, x1 + y1v + z1);
            *(float2*)(out + (size_t)n * 16 + 2 * hl) = o;
        }
    }
}

// =============================== launch ====================================
extern "C" void kernel_launch(void* const* d_in, const int* in_sizes, int n_in,
                              void* d_out, int out_size)
{
    const int*    row_ptr = (const int*)d_in[0];    // int32 (JAX x64 disabled)
    const int*    col_idx = (const int*)d_in[1];
    const float*  x       = (const float*)d_in[2];
    const float2* p       = (const float2*)d_in[3];
    const float*  mu      = (const float*)d_in[4];
    const float*  sg      = (const float*)d_in[5];
    const float*  W1      = (const float*)d_in[6];
    const float*  W2      = (const float*)d_in[7];

    const int n_nodes = in_sizes[0] - 1;

    void *xhp, *y2p;
    cudaGetSymbolAddress(&xhp, g_xh);
    cudaGetSymbolAddress(&y2p, g_y2);

    constexpr int NWARP = 8;
    constexpr int GRP   = 8;
    const int gblocks = (n_nodes + NWARP * GRP - 1) / (NWARP * GRP);
    const int fblocks = (n_nodes + 63) / 64;

    constexpr int FUSED_SMEM = 50688;
    cudaFuncSetAttribute(fused_l1_kernel,
                         cudaFuncAttributeMaxDynamicSharedMemorySize, FUSED_SMEM);

    // XCVT: x -> fp16 rows
    const int n4 = n_nodes * 16;
    xcvt_kernel<<<(n4 + 255) / 256, 256>>>((const float4*)x, (uint2*)xhp, n4);

    // FUSED layer 1: gather(xh) -> mma1 -> mma2 -> y2
    fused_l1_kernel<<<fblocks, 256, FUSED_SMEM>>>(
        row_ptr, col_idx, p, mu, sg, (const uint4*)xhp, W1, W2,
        (unsigned*)y2p, n_nodes);

    // G2: out = gather(y2)
    gather_h16<NWARP, GRP><<<gblocks, NWARP * 32>>>(
        row_ptr, col_idx, p, mu, sg, (const uint4*)y2p, (float*)d_out, n_nodes);
}

// round 17
// speedup vs baseline: 1.3520x; 1.1000x over previous
#include <cuda_runtime.h>
#include <cuda_fp16.h>
#include <cstddef>
#include <cstdint>

// ---------------------------------------------------------------------------
// GMM (MoNet) graph conv — 3-kernel pipeline, both layers fused gather+mma:
//   XCVT:   xh = fp16(x)  [N][64] halves (128B rows), 4 loads/thread
//   FUSED1: per 64-node CTA: Az[n,3,64] = gather(xh), mma (K=192) -> h fp16
//   FUSED2: per 64-node CTA: Az[n,3,32] = gather(h),  mma (K=96)  -> out f32
// ---------------------------------------------------------------------------

#define MAXN 131072
__device__ __half g_xh[MAXN * 64];   // x fp16, 128B rows
__device__ __half g_h [MAXN * 32];   // h fp16, 64B rows

typedef unsigned long long ull;

__device__ __forceinline__ ull pk2(float x, float y) {
    ull r; asm("mov.b64 %0, {%1,%2};" : "=l"(r) : "f"(x), "f"(y)); return r;
}
__device__ __forceinline__ void upk2(ull v, float& x, float& y) {
    asm("mov.b64 {%0,%1}, %2;" : "=f"(x), "=f"(y) : "l"(v));
}
__device__ __forceinline__ void ffma2(ull& d, ull a, ull b) {
    asm("fma.rn.f32x2 %0, %1, %2, %0;" : "+l"(d) : "l"(a), "l"(b));
}

__device__ __forceinline__ void ldsm_x4(uint32_t& r0, uint32_t& r1,
                                        uint32_t& r2, uint32_t& r3, uint32_t a) {
    asm volatile("ldmatrix.sync.aligned.m8n8.x4.shared.b16 {%0,%1,%2,%3}, [%4];"
                 : "=r"(r0), "=r"(r1), "=r"(r2), "=r"(r3) : "r"(a));
}
__device__ __forceinline__ void ldsm_x2_t(uint32_t& r0, uint32_t& r1, uint32_t a) {
    asm volatile("ldmatrix.sync.aligned.m8n8.x2.trans.shared.b16 {%0,%1}, [%2];"
                 : "=r"(r0), "=r"(r1) : "r"(a));
}
__device__ __forceinline__ void mma16816(float* c,
    uint32_t a0, uint32_t a1, uint32_t a2, uint32_t a3, uint32_t b0, uint32_t b1) {
    asm volatile(
        "mma.sync.aligned.m16n8k16.row.col.f32.f16.f16.f32 "
        "{%0,%1,%2,%3}, {%4,%5,%6,%7}, {%8,%9}, {%0,%1,%2,%3};"
        : "+f"(c[0]), "+f"(c[1]), "+f"(c[2]), "+f"(c[3])
        : "r"(a0), "r"(a1), "r"(a2), "r"(a3), "r"(b0), "r"(b1));
}

// ============================== gaussians ==================================
#define LOAD_GAUSS_PARAMS()                                                   \
    const float m0_ = mu[0], m1_ = mu[1], m2_ = mu[2],                        \
                m3_ = mu[3], m4_ = mu[4], m5_ = mu[5];                        \
    float s_;                                                                 \
    s_ = sigma[0]; const float i0_ = 1.f/(s_*s_);                             \
    s_ = sigma[1]; const float i1_ = 1.f/(s_*s_);                             \
    s_ = sigma[2]; const float i2_ = 1.f/(s_*s_);                             \
    s_ = sigma[3]; const float i3_ = 1.f/(s_*s_);                             \
    s_ = sigma[4]; const float i4_ = 1.f/(s_*s_);                             \
    s_ = sigma[5]; const float i5_ = 1.f/(s_*s_);

#define GAUSS3(pv, g0, g1, g2) do {                                           \
    float dx_, dy_, q_;                                                       \
    dx_ = (pv).x - m0_; dy_ = (pv).y - m1_;                                   \
    q_ = dx_*dx_*i0_ + dy_*dy_*i1_; g0 = __expf(-0.5f * q_);                  \
    dx_ = (pv).x - m2_; dy_ = (pv).y - m3_;                                   \
    q_ = dx_*dx_*i2_ + dy_*dy_*i3_; g1 = __expf(-0.5f * q_);                  \
    dx_ = (pv).x - m4_; dy_ = (pv).y - m5_;                                   \
    q_ = dx_*dx_*i4_ + dy_*dy_*i5_; g2 = __expf(-0.5f * q_);                  \
} while (0)

// ======================= XCVT: x -> fp16 (MLP=4) ===========================
__global__ void xcvt_kernel(const float4* __restrict__ X, uint2* __restrict__ Xh,
                            int n4)
{
    const int i0 = blockIdx.x * 1024 + threadIdx.x;
    #pragma unroll
    for (int k = 0; k < 4; k++) {
        const int i = i0 + k * 256;
        if (i < n4) {
            const float4 v = X[i];
            __half2 h0 = __floats2half2_rn(v.x, v.y);
            __half2 h1 = __floats2half2_rn(v.z, v.w);
            uint2 o;
            o.x = *(const uint32_t*)&h0;
            o.y = *(const uint32_t*)&h1;
            Xh[i] = o;
        }
    }
}

// ============ FUSED1: gather(xh) -> Az -> mma (K=192) -> h fp16 ============
// 256 thr (8 warps), 64 nodes/CTA. smem:
//   [0:16384)      stg[8][128] float4 (phase1) / Wb1[192][40] half (phase3+)
//   [16384:41984)  Az[64][200] half
__global__ void __launch_bounds__(256)
fused_l1_kernel(const int* __restrict__ row_ptr, const int* __restrict__ col_idx,
                const float2* __restrict__ p,
                const float* __restrict__ mu, const float* __restrict__ sigma,
                const uint4* __restrict__ xh,   // [N][8] 16B chunks
                const float* __restrict__ W1,   // [192][32]
                unsigned* __restrict__ hout,    // h: [N][16] uint (64B rows)
                int n_nodes)
{
    constexpr int ASTR = 200;
    constexpr int W1S  = 40;

    extern __shared__ __align__(16) char dsm[];
    float4 (*stg)[128] = (float4 (*)[128])dsm;
    __half* Wb1 = (__half*)dsm;
    __half* Az  = (__half*)(dsm + 16384);

    const int tid  = threadIdx.x;
    const int lane = tid & 31;
    const int wid  = tid >> 5;
    const int blk0 = blockIdx.x * 64;
    const int base = blk0 + wid * 8;

    LOAD_GAUSS_PARAMS();

    // ---------------- phase 1: stage edge gaussians ----------------
    {
        const int b0  = min(base, n_nodes);
        const int ng  = max(0, min(8, n_nodes - base));
        const int e0  = row_ptr[b0];
        const int ecnt = (ng > 0) ? (row_ptr[b0 + ng] - e0) : 0;
        const bool fast = (ecnt <= 128);

        if (fast) {
            for (int j = lane; j < ecnt; j += 32) {
                const int e = e0 + j;
                const int c = col_idx[e];
                const float2 pv = __ldg(p + e);
                float g0, g1, g2; GAUSS3(pv, g0, g1, g2);
                stg[wid][j] = make_float4(g0, g1, g2, __int_as_float(c));
            }
        }
        __syncwarp();

        // ---------------- phase 2: gather -> Az fp16 ----------------
        const int s  = lane >> 3;
        const int hl = lane & 7;

        #pragma unroll
        for (int pi = 0; pi < 2; pi++) {
            const int local = wid * 8 + pi * 4 + s;
            const int n = blk0 + local;
            const bool valid = (n < n_nodes);
            const int nc  = valid ? n : b0;
            const int st  = __ldg(row_ptr + nc);
            const int deg = valid ? (__ldg(row_ptr + nc + 1) - st) : 0;

            ull a[3][4];
            #pragma unroll
            for (int k = 0; k < 3; k++)
                #pragma unroll
                for (int v4 = 0; v4 < 4; v4++) a[k][v4] = 0ull;

            if (fast) {
                const float4* sd = &stg[wid][st - e0];
                const bool u16 = __all_sync(0xffffffffu, deg == 16);
                #define F_BODY(J) do {                                        \
                    const float4 ed = sd[(J)];                                \
                    const int c = __float_as_int(ed.w);                       \
                    const uint4 v = __ldg(xh + (size_t)c * 8 + hl);           \
                    const float2 f0 = __half22float2(*(const __half2*)&v.x);  \
                    const float2 f1 = __half22float2(*(const __half2*)&v.y);  \
                    const float2 f2 = __half22float2(*(const __half2*)&v.z);  \
                    const float2 f3 = __half22float2(*(const __half2*)&v.w);  \
                    const ull hp0 = pk2(f0.x, f0.y);                          \
                    const ull hp1 = pk2(f1.x, f1.y);                          \
                    const ull hp2 = pk2(f2.x, f2.y);                          \
                    const ull hp3 = pk2(f3.x, f3.y);                          \
                    const ull w0 = pk2(ed.x, ed.x);                           \
                    const ull w1 = pk2(ed.y, ed.y);                           \
                    const ull w2 = pk2(ed.z, ed.z);                           \
                    ffma2(a[0][0], w0, hp0); ffma2(a[0][1], w0, hp1);         \
                    ffma2(a[0][2], w0, hp2); ffma2(a[0][3], w0, hp3);         \
                    ffma2(a[1][0], w1, hp0); ffma2(a[1][1], w1, hp1);         \
                    ffma2(a[1][2], w1, hp2); ffma2(a[1][3], w1, hp3);         \
                    ffma2(a[2][0], w2, hp0); ffma2(a[2][1], w2, hp1);         \
                    ffma2(a[2][2], w2, hp2); ffma2(a[2][3], w2, hp3);         \
                } while (0)
                if (u16) {
                    #pragma unroll
                    for (int j = 0; j < 16; j++) F_BODY(j);
                } else {
                    const int maxd = __reduce_max_sync(0xffffffffu, deg);
                    for (int j = 0; j < maxd; j++)
                        if (j < deg) F_BODY(j);
                }
                #undef F_BODY
            } else {
                const int maxd = __reduce_max_sync(0xffffffffu, deg);
                for (int j = 0; j < maxd; j++) {
                    if (j < deg) {
                        const int e = st + j;
                        const int c = __ldg(col_idx + e);
                        const float2 pv = __ldg(p + e);
                        float g0, g1, g2; GAUSS3(pv, g0, g1, g2);
                        const uint4 v = __ldg(xh + (size_t)c * 8 + hl);
                        const float2 f0 = __half22float2(*(const __half2*)&v.x);
                        const float2 f1 = __half22float2(*(const __half2*)&v.y);
                        const float2 f2 = __half22float2(*(const __half2*)&v.z);
                        const float2 f3 = __half22float2(*(const __half2*)&v.w);
                        const ull hp0 = pk2(f0.x, f0.y);
                        const ull hp1 = pk2(f1.x, f1.y);
                        const ull hp2 = pk2(f2.x, f2.y);
                        const ull hp3 = pk2(f3.x, f3.y);
                        ffma2(a[0][0], pk2(g0, g0), hp0); ffma2(a[0][1], pk2(g0, g0), hp1);
                        ffma2(a[0][2], pk2(g0, g0), hp2); ffma2(a[0][3], pk2(g0, g0), hp3);
                        ffma2(a[1][0], pk2(g1, g1), hp0); ffma2(a[1][1], pk2(g1, g1), hp1);
                        ffma2(a[1][2], pk2(g1, g1), hp2); ffma2(a[1][3], pk2(g1, g1), hp3);
                        ffma2(a[2][0], pk2(g2, g2), hp0); ffma2(a[2][1], pk2(g2, g2), hp1);
                        ffma2(a[2][2], pk2(g2, g2), hp2); ffma2(a[2][3], pk2(g2, g2), hp3);
                    }
                }
            }

            #pragma unroll
            for (int k = 0; k < 3; k++) {
                __half2 hh[4];
                #pragma unroll
                for (int v4 = 0; v4 < 4; v4++) {
                    float lo, hi; upk2(a[k][v4], lo, hi);
                    hh[v4] = __floats2half2_rn(lo, hi);
                }
                *(uint4*)&Az[local * ASTR + k * 64 + 8 * hl] = *(const uint4*)hh;
            }
        }
    }
    __syncthreads();

    // ---------------- phase 3: stage W1 over stg ----------------
    for (int i = tid; i < 192 * 32; i += 256) {
        const int q = i >> 5, h = i & 31;
        Wb1[q * W1S + h] = __float2half(W1[i]);
    }
    __syncthreads();

    // ---------------- phase 4: mma  h[64x32] = Az * Wb1 ----------------
    const int wm = wid >> 1;
    const int wn = wid & 1;
    const int g = lane >> 2, t = lane & 3;
    const uint32_t abase  = (uint32_t)__cvta_generic_to_shared(Az);
    const uint32_t w1base = (uint32_t)__cvta_generic_to_shared(Wb1);
    const int arow  = wm * 16 + (lane & 15);
    const int acol8 = 8 * (lane >> 4);
    const int brow  = lane & 15;

    float acc[2][4];
    #pragma unroll
    for (int ni = 0; ni < 2; ni++)
        #pragma unroll
        for (int c = 0; c < 4; c++) acc[ni][c] = 0.f;

    #pragma unroll
    for (int kt = 0; kt < 12; kt++) {
        const int k0 = kt * 16;
        uint32_t a0, a1, a2, a3;
        ldsm_x4(a0, a1, a2, a3, abase + (arow * ASTR + k0 + acol8) * 2);
        #pragma unroll
        for (int ni = 0; ni < 2; ni++) {
            uint32_t b0, b1;
            ldsm_x2_t(b0, b1, w1base + ((k0 + brow) * W1S + wn * 16 + ni * 8) * 2);
            mma16816(acc[ni], a0, a1, a2, a3, b0, b1);
        }
    }

    // h out: row g / g+8, col wn*16 + ni*8 + 2t (half2 index /2)
    #pragma unroll
    for (int ni = 0; ni < 2; ni++) {
        const int ci = (wn * 16 + ni * 8 + 2 * t) >> 1;   // half2 index 0..15
        const int n0 = blk0 + wm * 16 + g;
        if (n0 < n_nodes) {
            const __half2 hv = __floats2half2_rn(acc[ni][0], acc[ni][1]);
            hout[(size_t)n0 * 16 + ci] = *(const unsigned*)&hv;
        }
        if (n0 + 8 < n_nodes) {
            const __half2 hv = __floats2half2_rn(acc[ni][2], acc[ni][3]);
            hout[(size_t)(n0 + 8) * 16 + ci] = *(const unsigned*)&hv;
        }
    }
}

// ============ FUSED2: gather(h) -> Az -> mma (K=96) -> out f32 =============
// 256 thr (8 warps), 64 nodes/CTA. smem:
//   [0:16384)      stg[8][128] float4 (phase1) / W2s[96][40] half (phase3+)
//   [16384:29696)  Az[64][104] half
__global__ void __launch_bounds__(256)
fused_l2_kernel(const int* __restrict__ row_ptr, const int* __restrict__ col_idx,
                const float2* __restrict__ p,
                const float* __restrict__ mu, const float* __restrict__ sigma,
                const uint4* __restrict__ h,    // [N][4] 16B chunks (64B rows)
                const float* __restrict__ W2,   // [3][32][16]
                float* __restrict__ out,        // [N][16] f32
                int n_nodes)
{
    constexpr int ASTR = 104;   // 52-word rows (20-bank shift, conflict-free)
    constexpr int W2S  = 40;

    extern __shared__ __align__(16) char dsm[];
    float4 (*stg)[128] = (float4 (*)[128])dsm;
    __half* W2s = (__half*)dsm;
    __half* Az  = (__half*)(dsm + 16384);

    const int tid  = threadIdx.x;
    const int lane = tid & 31;
    const int wid  = tid >> 5;
    const int blk0 = blockIdx.x * 64;
    const int base = blk0 + wid * 8;

    LOAD_GAUSS_PARAMS();

    // ---------------- phase 1: stage edge gaussians ----------------
    {
        const int b0  = min(base, n_nodes);
        const int ng  = max(0, min(8, n_nodes - base));
        const int e0  = row_ptr[b0];
        const int ecnt = (ng > 0) ? (row_ptr[b0 + ng] - e0) : 0;
        const bool fast = (ecnt <= 128);

        if (fast) {
            for (int j = lane; j < ecnt; j += 32) {
                const int e = e0 + j;
                const int c = col_idx[e];
                const float2 pv = __ldg(p + e);
                float g0, g1, g2; GAUSS3(pv, g0, g1, g2);
                stg[wid][j] = make_float4(g0, g1, g2, __int_as_float(c));
            }
        }
        __syncwarp();

        // ------ phase 2: gather -> Az fp16 (4 lanes/node, 8 nodes/pass) ----
        const int s  = lane >> 2;            // node slot 0..7
        const int hl = lane & 3;             // 16B chunk of 64B h row
        const int local = wid * 8 + s;
        const int n = blk0 + local;
        const bool valid = (n < n_nodes);
        const int nc  = valid ? n : b0;
        const int st  = __ldg(row_ptr + nc);
        const int deg = valid ? (__ldg(row_ptr + nc + 1) - st) : 0;

        ull a[3][4];
        #pragma unroll
        for (int k = 0; k < 3; k++)
            #pragma unroll
            for (int v4 = 0; v4 < 4; v4++) a[k][v4] = 0ull;

        if (fast) {
            const float4* sd = &stg[wid][st - e0];
            const bool u16 = __all_sync(0xffffffffu, deg == 16);
            #define F2_BODY(J) do {                                           \
                const float4 ed = sd[(J)];                                    \
                const int c = __float_as_int(ed.w);                           \
                const uint4 v = __ldg(h + (size_t)c * 4 + hl);                \
                const float2 f0 = __half22float2(*(const __half2*)&v.x);      \
                const float2 f1 = __half22float2(*(const __half2*)&v.y);      \
                const float2 f2 = __half22float2(*(const __half2*)&v.z);      \
                const float2 f3 = __half22float2(*(const __half2*)&v.w);      \
                const ull hp0 = pk2(f0.x, f0.y);                              \
                const ull hp1 = pk2(f1.x, f1.y);                              \
                const ull hp2 = pk2(f2.x, f2.y);                              \
                const ull hp3 = pk2(f3.x, f3.y);                              \
                const ull w0 = pk2(ed.x, ed.x);                               \
                const ull w1 = pk2(ed.y, ed.y);                               \
                const ull w2 = pk2(ed.z, ed.z);                               \
                ffma2(a[0][0], w0, hp0); ffma2(a[0][1], w0, hp1);             \
                ffma2(a[0][2], w0, hp2); ffma2(a[0][3], w0, hp3);             \
                ffma2(a[1][0], w1, hp0); ffma2(a[1][1], w1, hp1);             \
                ffma2(a[1][2], w1, hp2); ffma2(a[1][3], w1, hp3);             \
                ffma2(a[2][0], w2, hp0); ffma2(a[2][1], w2, hp1);             \
                ffma2(a[2][2], w2, hp2); ffma2(a[2][3], w2, hp3);             \
            } while (0)
            if (u16) {
                #pragma unroll
                for (int j = 0; j < 16; j++) F2_BODY(j);
            } else {
                const int maxd = __reduce_max_sync(0xffffffffu, deg);
                for (int j = 0; j < maxd; j++)
                    if (j < deg) F2_BODY(j);
            }
            #undef F2_BODY
        } else {
            const int maxd = __reduce_max_sync(0xffffffffu, deg);
            for (int j = 0; j < maxd; j++) {
                if (j < deg) {
                    const int e = st + j;
                    const int c = __ldg(col_idx + e);
                    const float2 pv = __ldg(p + e);
                    float g0, g1, g2; GAUSS3(pv, g0, g1, g2);
                    const uint4 v = __ldg(h + (size_t)c * 4 + hl);
                    const float2 f0 = __half22float2(*(const __half2*)&v.x);
                    const float2 f1 = __half22float2(*(const __half2*)&v.y);
                    const float2 f2 = __half22float2(*(const __half2*)&v.z);
                    const float2 f3 = __half22float2(*(const __half2*)&v.w);
                    const ull hp0 = pk2(f0.x, f0.y);
                    const ull hp1 = pk2(f1.x, f1.y);
                    const ull hp2 = pk2(f2.x, f2.y);
                    const ull hp3 = pk2(f3.x, f3.y);
                    ffma2(a[0][0], pk2(g0, g0), hp0); ffma2(a[0][1], pk2(g0, g0), hp1);
                    ffma2(a[0][2], pk2(g0, g0), hp2); ffma2(a[0][3], pk2(g0, g0), hp3);
                    ffma2(a[1][0], pk2(g1, g1), hp0); ffma2(a[1][1], pk2(g1, g1), hp1);
                    ffma2(a[1][2], pk2(g1, g1), hp2); ffma2(a[1][3], pk2(g1, g1), hp3);
                    ffma2(a[2][0], pk2(g2, g2), hp0); ffma2(a[2][1], pk2(g2, g2), hp1);
                    ffma2(a[2][2], pk2(g2, g2), hp2); ffma2(a[2][3], pk2(g2, g2), hp3);
                }
            }
        }

        // Az[local][k*32 + 8hl .. +7]
        #pragma unroll
        for (int k = 0; k < 3; k++) {
            __half2 hh[4];
            #pragma unroll
            for (int v4 = 0; v4 < 4; v4++) {
                float lo, hi; upk2(a[k][v4], lo, hi);
                hh[v4] = __floats2half2_rn(lo, hi);
            }
            *(uint4*)&Az[local * ASTR + k * 32 + 8 * hl] = *(const uint4*)hh;
        }
    }
    __syncthreads();

    // ---------------- phase 3: stage W2stack over stg ----------------
    // W2s[q][o] = W2[k][f][o], q = k*32 + f
    for (int i = tid; i < 96 * 16; i += 256) {
        const int q = i >> 4, o = i & 15;
        W2s[q * W2S + o] = __float2half(W2[(size_t)q * 16 + o]);
    }
    __syncthreads();

    // ---------------- phase 4: mma  out[64x16] = Az * W2s (K=96) ----------
    const int wm = wid >> 1;
    const int wn = wid & 1;             // 8-col halves of the 16 outputs
    const int g = lane >> 2, t = lane & 3;
    const uint32_t abase = (uint32_t)__cvta_generic_to_shared(Az);
    const uint32_t wbase = (uint32_t)__cvta_generic_to_shared(W2s);
    const int arow  = wm * 16 + (lane & 15);
    const int acol8 = 8 * (lane >> 4);
    const int brow  = lane & 15;

    float acc[4];
    #pragma unroll
    for (int c = 0; c < 4; c++) acc[c] = 0.f;

    #pragma unroll
    for (int kt = 0; kt < 6; kt++) {
        const int k0 = kt * 16;
        uint32_t a0, a1, a2, a3;
        ldsm_x4(a0, a1, a2, a3, abase + (arow * ASTR + k0 + acol8) * 2);
        uint32_t b0, b1;
        ldsm_x2_t(b0, b1, wbase + ((k0 + brow) * W2S + wn * 8) * 2);
        mma16816(acc, a0, a1, a2, a3, b0, b1);
    }

    // out: row g / g+8, cols wn*8 + 2t, 2t+1 (f32)
    {
        const int col = wn * 8 + 2 * t;
        const int n0 = blk0 + wm * 16 + g;
        if (n0 < n_nodes)
            *(float2*)(out + (size_t)n0 * 16 + col) = make_float2(acc[0], acc[1]);
        if (n0 + 8 < n_nodes)
            *(float2*)(out + (size_t)(n0 + 8) * 16 + col) = make_float2(acc[2], acc[3]);
    }
}

// =============================== launch ====================================
extern "C" void kernel_launch(void* const* d_in, const int* in_sizes, int n_in,
                              void* d_out, int out_size)
{
    const int*    row_ptr = (const int*)d_in[0];    // int32 (JAX x64 disabled)
    const int*    col_idx = (const int*)d_in[1];
    const float*  x       = (const float*)d_in[2];
    const float2* p       = (const float2*)d_in[3];
    const float*  mu      = (const float*)d_in[4];
    const float*  sg      = (const float*)d_in[5];
    const float*  W1      = (const float*)d_in[6];
    const float*  W2      = (const float*)d_in[7];

    const int n_nodes = in_sizes[0] - 1;

    void *xhp, *hp;
    cudaGetSymbolAddress(&xhp, g_xh);
    cudaGetSymbolAddress(&hp,  g_h);

    const int fblocks = (n_nodes + 63) / 64;

    constexpr int SMEM1 = 41984;   // stg/Wb1 (16384) + Az (25600)
    constexpr int SMEM2 = 29696;   // stg/W2s (16384) + Az (13312)
    cudaFuncSetAttribute(fused_l1_kernel,
                         cudaFuncAttributeMaxDynamicSharedMemorySize, SMEM1);
    cudaFuncSetAttribute(fused_l2_kernel,
                         cudaFuncAttributeMaxDynamicSharedMemorySize, SMEM2);

    // XCVT: x -> fp16 rows (4 independent loads per thread)
    const int n4 = n_nodes * 16;
    xcvt_kernel<<<(n4 + 1023) / 1024, 256>>>((const float4*)x, (uint2*)xhp, n4);

    // FUSED1: gather(xh) -> mma -> h fp16
    fused_l1_kernel<<<fblocks, 256, SMEM1>>>(
        row_ptr, col_idx, p, mu, sg, (const uint4*)xhp, W1,
        (unsigned*)hp, n_nodes);

    // FUSED2: gather(h) -> mma -> out f32
    fused_l2_kernel<<<fblocks, 256, SMEM2>>>(
        row_ptr, col_idx, p, mu, sg, (const uint4*)hp, W2,
        (float*)d_out, n_nodes);
}